// round 15
// baseline (speedup 1.0000x reference)
#include <cuda_runtime.h>
#include <cuda_fp16.h>
#include <math.h>
#include <stdint.h>

constexpr int BATCH  = 4;
constexpr int SEQ    = 2048;
constexpr int DMODEL = 512;
constexpr int NH     = 8;
constexpr int HD     = 64;
constexpr int DINNER = NH * HD;        // 512
constexpr int ROWS   = BATCH * SEQ;    // 8192

constexpr int NSPLIT = 2;              // attention split-K factor
constexpr size_t OSZ = (size_t)ROWS * DINNER;
constexpr int LSZ = BATCH * NH * SEQ;

// Scratch (global device arrays; no allocations allowed)
__device__ __half g_xn16[ROWS * DMODEL];
__device__ __half g_wqkvT[3 * DINNER * DMODEL];   // [N=1536][K=512]
__device__ __half g_woutT[DMODEL * DINNER];       // [N=512][K=512]
__device__ float2 g_rope[SEQ * 32];               // (cos, sin) per (n, pair)
__device__ __half g_q16[(size_t)BATCH * NH * SEQ * HD];
__device__ __half g_k16[(size_t)BATCH * NH * SEQ * HD];
__device__ __half g_v16[(size_t)BATCH * NH * SEQ * HD];
__device__ __half g_opart[NSPLIT * OSZ];          // normalized fp16 partials
__device__ float  g_lpart[NSPLIT * LSZ];          // split-K partial l

// ===========================================================================
// Helpers
// ===========================================================================
__device__ __forceinline__ float ex2(float x) {
    float y;
    asm("ex2.approx.f32 %0, %1;" : "=f"(y) : "f"(x));
    return y;
}

__device__ __forceinline__ uint32_t smem_u32(const void* p) {
    uint32_t a;
    asm("{ .reg .u64 t; cvta.to.shared.u64 t, %1; cvt.u32.u64 %0, t; }"
        : "=r"(a) : "l"(p));
    return a;
}

__device__ __forceinline__ uint32_t h2pack(float a, float b) {
    __half2 h = __floats2half2_rn(a, b);
    return *(uint32_t*)&h;
}

__device__ __forceinline__ void mma_f16(float d[4], const uint32_t a[4],
                                        uint32_t b0, uint32_t b1) {
    asm volatile(
        "mma.sync.aligned.m16n8k16.row.col.f32.f16.f16.f32 "
        "{%0,%1,%2,%3}, {%4,%5,%6,%7}, {%8,%9}, {%0,%1,%2,%3};"
        : "+f"(d[0]), "+f"(d[1]), "+f"(d[2]), "+f"(d[3])
        : "r"(a[0]), "r"(a[1]), "r"(a[2]), "r"(a[3]), "r"(b0), "r"(b1));
}

__device__ __forceinline__ void ldm_x4(uint32_t r[4], uint32_t addr) {
    asm volatile(
        "ldmatrix.sync.aligned.m8n8.x4.shared.b16 {%0,%1,%2,%3}, [%4];"
        : "=r"(r[0]), "=r"(r[1]), "=r"(r[2]), "=r"(r[3]) : "r"(addr));
}

__device__ __forceinline__ void ldm_x4t(uint32_t r[4], uint32_t addr) {
    asm volatile(
        "ldmatrix.sync.aligned.m8n8.x4.trans.shared.b16 {%0,%1,%2,%3}, [%4];"
        : "=r"(r[0]), "=r"(r[1]), "=r"(r[2]), "=r"(r[3]) : "r"(addr));
}

__device__ __forceinline__ void cp16(uint32_t dst, const void* src) {
    asm volatile("cp.async.cg.shared.global [%0], [%1], 16;"
                 :: "r"(dst), "l"(src));
}
#define CP_COMMIT() asm volatile("cp.async.commit_group;" ::: "memory")
#define CP_WAIT2()  asm volatile("cp.async.wait_group 2;" ::: "memory")
#define CP_WAIT1()  asm volatile("cp.async.wait_group 1;" ::: "memory")
#define CP_WAIT0()  asm volatile("cp.async.wait_group 0;" ::: "memory")

// ===========================================================================
// Fused prep kernel: block-dispatched rmsnorm (2 rows/block, float4) /
// wtrans x2 / rope table.
// blocks [0,4096): rmsnorm rows 2*blk, 2*blk+1
// blocks [4096,4288): wtrans w_qkv; [4288,4352): wtrans w_out; [4352,4608): rope
// ===========================================================================
__device__ __forceinline__ void wtrans_body(const float* __restrict__ W,
                                            __half* __restrict__ Wt,
                                            int K, int N, int n0, int k0,
                                            float (*ts)[65]) {
    int tid = threadIdx.x;
    #pragma unroll
    for (int e = 0; e < 16; e++) {
        int idx = tid + e * 256;
        int kl = idx >> 6, nl = idx & 63;
        ts[kl][nl] = W[(size_t)(k0 + kl) * N + n0 + nl];
    }
    __syncthreads();
    #pragma unroll
    for (int e = 0; e < 8; e++) {
        int idx = tid + e * 256;
        int nl = idx >> 5, kp = idx & 31;
        *(__half2*)(Wt + (size_t)(n0 + nl) * K + k0 + 2 * kp) =
            __floats2half2_rn(ts[2 * kp][nl], ts[2 * kp + 1][nl]);
    }
}

__global__ void prep_kernel(const float* __restrict__ x,
                            const float* __restrict__ gamma,
                            const float* __restrict__ w_qkv,
                            const float* __restrict__ w_out,
                            __half* __restrict__ xn,
                            __half* __restrict__ wqkvT,
                            __half* __restrict__ woutT,
                            float2* __restrict__ rope) {
    __shared__ float ts[64][65];
    int blk = blockIdx.x, t = threadIdx.x;

    if (blk < ROWS / 2) {
        // RMSNorm: 2 rows per block, float4 loads. Warps 0-3 row0, 4-7 row1.
        int row = blk * 2 + (t >> 7);
        int tr = t & 127;
        float4 v = ((const float4*)(x + (size_t)row * DMODEL))[tr];
        float4 gv = ((const float4*)gamma)[tr];
        float local = v.x * v.x + v.y * v.y + v.z * v.z + v.w * v.w;
        #pragma unroll
        for (int o = 16; o > 0; o >>= 1)
            local += __shfl_xor_sync(0xffffffffu, local, o);
        int wid = t >> 5;
        if ((t & 31) == 0) ts[0][wid] = local;
        __syncthreads();
        int base = (t >> 7) * 4;
        float s = ts[0][base] + ts[0][base + 1] + ts[0][base + 2]
                + ts[0][base + 3];
        float scale = 22.62741699796952f / fmaxf(sqrtf(s), 1e-8f);  // sqrt(512)
        uint2 o2;
        o2.x = h2pack(v.x * scale * gv.x, v.y * scale * gv.y);
        o2.y = h2pack(v.z * scale * gv.z, v.w * scale * gv.w);
        *(uint2*)(xn + (size_t)row * DMODEL + tr * 4) = o2;
    } else if (blk < ROWS / 2 + 192) {
        int i = blk - ROWS / 2;                 // 24 x 8 tiles
        wtrans_body(w_qkv, wqkvT, DMODEL, 3 * DINNER,
                    (i % 24) * 64, (i / 24) * 64, ts);
    } else if (blk < ROWS / 2 + 192 + 64) {
        int i = blk - ROWS / 2 - 192;           // 8 x 8 tiles
        wtrans_body(w_out, woutT, DMODEL, DINNER,
                    (i & 7) * 64, (i >> 3) * 64, ts);
    } else {
        int gid = (blk - (ROWS / 2 + 256)) * 256 + t;
        int p = gid & 31, n = gid >> 5;
        float invf = powf(10000.0f, -(float)p / 32.0f);
        float sn, cs;
        sincosf((float)n * invf, &sn, &cs);
        rope[gid] = make_float2(cs, sn);
    }
}

// ===========================================================================
// fp16 tensor GEMM: CTA 128(M) x 64(N), BK=64, 256 threads (8 warps 4x2),
// warp tile 32x32 (3 CTAs/SM). 2-stage cp.async. Rows padded to 144B.
// MODE 0: A fp16, C fp32.
// MODE 1: A fp16, fused RoPE (table) epilogue -> q/k/v fp16.
// MODE 2: A = two normalized fp16 split-K partials combined on the fly
//         (weights l_s/sum l, per row; head h = k-step index), C fp32.
// ===========================================================================
constexpr int G_A_B     = 128 * 144;               // 18432
constexpr int G_STAGE_B = G_A_B + 64 * 144;        // 27648
constexpr int G_SMEM_B  = 2 * G_STAGE_B;           // 55296

template<int MODE>
__global__ void __launch_bounds__(256, 3) gemm16(
        const __half* __restrict__ A, const __half* __restrict__ Wt,
        float* __restrict__ C, __half* __restrict__ qo,
        __half* __restrict__ ko, __half* __restrict__ vo,
        const float2* __restrict__ rope, const float* __restrict__ lp,
        int M, int N, int K) {
    extern __shared__ char smraw[];
    uint32_t sb = smem_u32(smraw);
    int tid = threadIdx.x, lane = tid & 31, wid = tid >> 5;
    int g = lane >> 2, tig = lane & 3;
    int m0 = blockIdx.y * 128, n0 = blockIdx.x * 64;
    int wm = (wid & 3) * 32, wn = (wid >> 2) * 32;

    float acc[2][4][4] = {};
    int nst = K / 64;

    // A staging: MODE<2 cp.async; MODE2 LDG both partials + combine + STS
    auto stage_A = [&](int st) {
        int k0 = st * 64;
        if (MODE < 2) {
            uint32_t base = sb + (st & 1) * G_STAGE_B;
            #pragma unroll
            for (int e = 0; e < 4; e++) {
                int c = tid + e * 256;
                cp16(base + (c >> 3) * 144 + (c & 7) * 16,
                     A + (size_t)(m0 + (c >> 3)) * K + k0 + (c & 7) * 8);
            }
        } else {
            int h = st;                          // k-step == head
            char* base = smraw + (st & 1) * G_STAGE_B;
            #pragma unroll
            for (int e = 0; e < 4; e++) {
                int c = tid + e * 256;
                int r = c >> 3, cc = (c & 7) * 8;
                int gr = m0 + r;
                int n_ = gr & (SEQ - 1), b_ = gr >> 11;
                int li = (b_ * NH + h) * SEQ + n_;
                float l0 = __ldg(&lp[li]), l1 = __ldg(&lp[LSZ + li]);
                float it = 1.0f / (l0 + l1);
                float w0 = l0 * it, w1 = l1 * it;
                size_t off = (size_t)gr * DINNER + k0 + cc;
                uint4 a0 = *(const uint4*)(A + off);
                uint4 a1 = *(const uint4*)(A + OSZ + off);
                uint4 r4;
                #pragma unroll
                for (int j = 0; j < 4; j++) {
                    float2 f0 = __half22float2(((const __half2*)&a0)[j]);
                    float2 f1 = __half22float2(((const __half2*)&a1)[j]);
                    ((uint32_t*)&r4)[j] = h2pack(w0 * f0.x + w1 * f1.x,
                                                 w0 * f0.y + w1 * f1.y);
                }
                *(uint4*)(base + r * 144 + (c & 7) * 16) = r4;
            }
        }
    };
    auto stage_B = [&](int st) {
        int k0 = st * 64;
        uint32_t base = sb + (st & 1) * G_STAGE_B;
        #pragma unroll
        for (int e = 0; e < 2; e++) {
            int c = tid + e * 256;
            cp16(base + G_A_B + (c >> 3) * 144 + (c & 7) * 16,
                 Wt + (size_t)(n0 + (c >> 3)) * K + k0 + (c & 7) * 8);
        }
        CP_COMMIT();
    };

    stage_A(0); stage_B(0);
    stage_A(1); stage_B(1);

    for (int st = 0; st < nst; st++) {
        if (st + 2 <= nst) { CP_WAIT1(); } else { CP_WAIT0(); }
        __syncthreads();

        uint32_t sa_ = sb + (st & 1) * G_STAGE_B;
        uint32_t aoff = sa_ + (wm + (lane & 15)) * 144 + (lane >> 4) * 16;
        uint32_t boff = sa_ + G_A_B + (wn + (lane & 15)) * 144
                      + (lane >> 4) * 16;

        #pragma unroll
        for (int kc = 0; kc < 4; kc++) {
            uint32_t bf0[4], bf1[4];
            ldm_x4(bf0, boff + kc * 32);
            ldm_x4(bf1, boff + 16 * 144 + kc * 32);
            #pragma unroll
            for (int mt = 0; mt < 2; mt++) {
                uint32_t af[4];
                ldm_x4(af, aoff + mt * 16 * 144 + kc * 32);
                mma_f16(acc[mt][0], af, bf0[0], bf0[2]);
                mma_f16(acc[mt][1], af, bf0[1], bf0[3]);
                mma_f16(acc[mt][2], af, bf1[0], bf1[2]);
                mma_f16(acc[mt][3], af, bf1[1], bf1[3]);
            }
        }
        __syncthreads();

        if (st + 2 < nst) {
            stage_A(st + 2);
            stage_B(st + 2);
        }
    }

    if (MODE != 1) {
        #pragma unroll
        for (int mt = 0; mt < 2; mt++)
            #pragma unroll
            for (int nb = 0; nb < 4; nb++) {
                int r = m0 + wm + mt * 16 + g;
                int c = n0 + wn + nb * 8 + 2 * tig;
                float* t = acc[mt][nb];
                *(float2*)&C[(size_t)r * N + c]       = make_float2(t[0], t[1]);
                *(float2*)&C[(size_t)(r + 8) * N + c] = make_float2(t[2], t[3]);
            }
    } else {
        int which = n0 >> 9;
        const float QS = 0.125f * 1.44269504088896341f;
        #pragma unroll
        for (int nb = 0; nb < 4; nb++) {
            int cg = n0 + wn + nb * 8 + 2 * tig;
            int h = (cg & 511) >> 6, d = cg & 63;
            int p = d >> 1;
            #pragma unroll
            for (int mt = 0; mt < 2; mt++) {
                int r0 = m0 + wm + mt * 16 + g;
                int n_ = r0 & (SEQ - 1), b_ = r0 >> 11;
                size_t o0 = ((size_t)(b_ * NH + h) * SEQ + n_) * HD + d;
                float* t = acc[mt][nb];
                if (which == 2) {
                    *(__half2*)(vo + o0) = __floats2half2_rn(t[0], t[1]);
                    *(__half2*)(vo + o0 + 8 * HD) =
                        __floats2half2_rn(t[2], t[3]);
                } else {
                    float2 cs0 = rope[n_ * 32 + p];
                    float2 cs1 = rope[(n_ + 8) * 32 + p];
                    if (which == 0) {
                        *(__half2*)(qo + o0) = __floats2half2_rn(
                            (t[0] * cs0.x - t[1] * cs0.y) * QS,
                            (t[1] * cs0.x + t[0] * cs0.y) * QS);
                        *(__half2*)(qo + o0 + 8 * HD) = __floats2half2_rn(
                            (t[2] * cs1.x - t[3] * cs1.y) * QS,
                            (t[3] * cs1.x + t[2] * cs1.y) * QS);
                    } else {
                        *(__half2*)(ko + o0) = __floats2half2_rn(
                            t[0] * cs0.x - t[1] * cs0.y,
                            t[1] * cs0.x + t[0] * cs0.y);
                        *(__half2*)(ko + o0 + 8 * HD) = __floats2half2_rn(
                            t[2] * cs1.x - t[3] * cs1.y,
                            t[3] * cs1.x + t[2] * cs1.y);
                    }
                }
            }
        }
    }
}

// ===========================================================================
// fp16 tensor flash attention, split-K=2, one-pass no-max softmax.
// CTA: 128 queries x 1024 keys (16 tiles); 4 warps x 32 rows; 3-stage
// cp.async K/V. P never touches smem. Writes NORMALIZED fp16 O partial
// (O_s / l_s) + fp32 l. 3 CTAs/SM.
// ===========================================================================
constexpr int KT_SPLIT  = SEQ / 64 / NSPLIT;     // 16 key tiles per split
constexpr int A_STAGE_B = 2 * 64 * 144;          // K(9216)+V(9216) bytes
constexpr int A_SMEM_B  = 3 * A_STAGE_B;         // 55296 bytes

__global__ void __launch_bounds__(128, 3) attn16(
        const __half* __restrict__ q, const __half* __restrict__ k,
        const __half* __restrict__ v, __half* __restrict__ opart,
        float* __restrict__ lpart) {
    extern __shared__ char smraw[];
    uint32_t sb = smem_u32(smraw);

    int tid = threadIdx.x, lane = tid & 31, w = tid >> 5;
    int g = lane >> 2, tig = lane & 3;
    int wq = w * 32;

    int q0 = blockIdx.x * 128;
    int h = blockIdx.y;
    int b = blockIdx.z >> 1, sp = blockIdx.z & 1;
    int tbase = sp * KT_SPLIT;

    const __half* qb = q + ((size_t)(b * NH + h)) * SEQ * HD;
    const __half* kb = k + ((size_t)(b * NH + h)) * SEQ * HD;
    const __half* vb = v + ((size_t)(b * NH + h)) * SEQ * HD;

    int crow[4], cch[4];
    #pragma unroll
    for (int e = 0; e < 4; e++) {
        int c = tid + e * 128;
        crow[e] = c >> 3;
        cch[e] = c & 7;
    }

    // Q fragments in registers (pre-scaled fp16 by producer)
    uint32_t qa[2][4][4];
    #pragma unroll
    for (int mb = 0; mb < 2; mb++) {
        const uint32_t* q0r =
            (const uint32_t*)(qb + (size_t)(q0 + wq + mb * 16 + g) * HD);
        const uint32_t* q8r =
            (const uint32_t*)(qb + (size_t)(q0 + wq + mb * 16 + g + 8) * HD);
        #pragma unroll
        for (int kc = 0; kc < 4; kc++) {
            qa[mb][kc][0] = q0r[kc * 8 + tig];
            qa[mb][kc][1] = q8r[kc * 8 + tig];
            qa[mb][kc][2] = q0r[kc * 8 + 4 + tig];
            qa[mb][kc][3] = q8r[kc * 8 + 4 + tig];
        }
    }

    float oa[2][8][4] = {};
    float lr[2][2] = {};

    #pragma unroll
    for (int st = 0; st < 3; st++) {
        uint32_t base = sb + st * A_STAGE_B;
        #pragma unroll
        for (int e = 0; e < 4; e++) {
            uint32_t d = base + crow[e] * 144 + cch[e] * 16;
            cp16(d, kb + (size_t)((tbase + st) * 64 + crow[e]) * HD
                    + cch[e] * 8);
            cp16(d + 64 * 144,
                 vb + (size_t)((tbase + st) * 64 + crow[e]) * HD + cch[e] * 8);
        }
        CP_COMMIT();
    }

    for (int kt = 0; kt < KT_SPLIT; kt++) {
        if (kt + 3 <= KT_SPLIT) { CP_WAIT2(); }
        else if (kt + 2 <= KT_SPLIT) { CP_WAIT1(); }
        else { CP_WAIT0(); }
        __syncthreads();

        uint32_t kst = sb + (kt % 3) * A_STAGE_B;
        uint32_t kfrag = kst + (lane & 15) * 144 + (lane >> 4) * 16;
        uint32_t vfrag = kst + 64 * 144 + (lane & 15) * 144 + (lane >> 4) * 16;

        #pragma unroll
        for (int hc = 0; hc < 2; hc++) {     // two 32-key halves
            float sa[2][4][4] = {};
            #pragma unroll
            for (int nt16 = 0; nt16 < 2; nt16++) {
                #pragma unroll
                for (int kc = 0; kc < 4; kc++) {
                    uint32_t f[4];
                    ldm_x4(f, kfrag + (hc * 32 + nt16 * 16) * 144 + kc * 32);
                    #pragma unroll
                    for (int mb = 0; mb < 2; mb++) {
                        mma_f16(sa[mb][nt16 * 2],     qa[mb][kc], f[0], f[2]);
                        mma_f16(sa[mb][nt16 * 2 + 1], qa[mb][kc], f[1], f[3]);
                    }
                }
            }

            #pragma unroll
            for (int mb = 0; mb < 2; mb++)
                #pragma unroll
                for (int nb = 0; nb < 4; nb++) {
                    sa[mb][nb][0] = ex2(sa[mb][nb][0]);
                    sa[mb][nb][1] = ex2(sa[mb][nb][1]);
                    sa[mb][nb][2] = ex2(sa[mb][nb][2]);
                    sa[mb][nb][3] = ex2(sa[mb][nb][3]);
                    lr[mb][0] += sa[mb][nb][0] + sa[mb][nb][1];
                    lr[mb][1] += sa[mb][nb][2] + sa[mb][nb][3];
                }

            #pragma unroll
            for (int kcl = 0; kcl < 2; kcl++) {
                uint32_t paf[2][4];
                #pragma unroll
                for (int mb = 0; mb < 2; mb++) {
                    paf[mb][0] = h2pack(sa[mb][2 * kcl][0], sa[mb][2 * kcl][1]);
                    paf[mb][1] = h2pack(sa[mb][2 * kcl][2], sa[mb][2 * kcl][3]);
                    paf[mb][2] = h2pack(sa[mb][2 * kcl + 1][0],
                                        sa[mb][2 * kcl + 1][1]);
                    paf[mb][3] = h2pack(sa[mb][2 * kcl + 1][2],
                                        sa[mb][2 * kcl + 1][3]);
                }
                #pragma unroll
                for (int ntp = 0; ntp < 4; ntp++) {
                    uint32_t vf[4];
                    ldm_x4t(vf, vfrag + (hc * 32 + kcl * 16) * 144 + ntp * 32);
                    #pragma unroll
                    for (int mb = 0; mb < 2; mb++) {
                        mma_f16(oa[mb][ntp * 2],     paf[mb], vf[0], vf[1]);
                        mma_f16(oa[mb][ntp * 2 + 1], paf[mb], vf[2], vf[3]);
                    }
                }
            }
        }
        __syncthreads();

        if (kt + 3 < KT_SPLIT) {
            uint32_t base = sb + (kt % 3) * A_STAGE_B;
            #pragma unroll
            for (int e = 0; e < 4; e++) {
                uint32_t d = base + crow[e] * 144 + cch[e] * 16;
                cp16(d, kb + (size_t)((tbase + kt + 3) * 64 + crow[e]) * HD
                        + cch[e] * 8);
                cp16(d + 64 * 144,
                     vb + (size_t)((tbase + kt + 3) * 64 + crow[e]) * HD
                        + cch[e] * 8);
            }
            CP_COMMIT();
        }
    }

    // Write NORMALIZED fp16 partial O + fp32 partial l
    __half* od = opart + (size_t)sp * OSZ;
    float* ld = lpart + sp * LSZ;
    #pragma unroll
    for (int mb = 0; mb < 2; mb++) {
        float l0 = lr[mb][0], l1 = lr[mb][1];
        l0 += __shfl_xor_sync(0xffffffffu, l0, 1);
        l0 += __shfl_xor_sync(0xffffffffu, l0, 2);
        l1 += __shfl_xor_sync(0xffffffffu, l1, 1);
        l1 += __shfl_xor_sync(0xffffffffu, l1, 2);
        float inv0 = 1.0f / l0, inv1 = 1.0f / l1;
        int rq = q0 + wq + mb * 16 + g;
        size_t base0 = ((size_t)b * SEQ + rq) * DINNER + h * HD;
        #pragma unroll
        for (int nb = 0; nb < 8; nb++) {
            int c = nb * 8 + 2 * tig;
            *(uint32_t*)(od + base0 + c) =
                h2pack(oa[mb][nb][0] * inv0, oa[mb][nb][1] * inv0);
            *(uint32_t*)(od + base0 + (size_t)8 * DINNER + c) =
                h2pack(oa[mb][nb][2] * inv1, oa[mb][nb][3] * inv1);
        }
        if (tig == 0) {
            ld[(b * NH + h) * SEQ + rq]     = l0;
            ld[(b * NH + h) * SEQ + rq + 8] = l1;
        }
    }
}

// ===========================================================================
extern "C" void kernel_launch(void* const* d_in, const int* in_sizes, int n_in,
                              void* d_out, int out_size) {
    const float* x      = (const float*)d_in[0];
    const float* gamma  = (const float*)d_in[1];
    const float* w_qkv  = (const float*)d_in[2];
    const float* w_out  = (const float*)d_in[3];
    float* out = (float*)d_out;

    __half *xn, *wqkvT, *woutT, *qq, *kk, *vv, *opart;
    float *lpart;
    float2 *rope;
    cudaGetSymbolAddress((void**)&xn,    g_xn16);
    cudaGetSymbolAddress((void**)&wqkvT, g_wqkvT);
    cudaGetSymbolAddress((void**)&woutT, g_woutT);
    cudaGetSymbolAddress((void**)&rope,  g_rope);
    cudaGetSymbolAddress((void**)&qq,    g_q16);
    cudaGetSymbolAddress((void**)&kk,    g_k16);
    cudaGetSymbolAddress((void**)&vv,    g_v16);
    cudaGetSymbolAddress((void**)&opart, g_opart);
    cudaGetSymbolAddress((void**)&lpart, g_lpart);

    cudaFuncSetAttribute(gemm16<1>,
                         cudaFuncAttributeMaxDynamicSharedMemorySize, G_SMEM_B);
    cudaFuncSetAttribute(gemm16<2>,
                         cudaFuncAttributeMaxDynamicSharedMemorySize, G_SMEM_B);
    cudaFuncSetAttribute(attn16,
                         cudaFuncAttributeMaxDynamicSharedMemorySize, A_SMEM_B);

    // Fused prep: rmsnorm (2 rows/block) + weight transposes + rope table
    prep_kernel<<<ROWS / 2 + 192 + 64 + 256, 256>>>(
        x, gamma, w_qkv, w_out, xn, wqkvT, woutT, rope);

    // QKV GEMM with fused RoPE/split/fp16 epilogue
    gemm16<1><<<dim3(3 * DINNER / 64, ROWS / 128), 256, G_SMEM_B>>>(
        xn, wqkvT, nullptr, qq, kk, vv, rope, nullptr,
        ROWS, 3 * DINNER, DMODEL);

    // split-K=2 attention (fp16 normalized partials)
    attn16<<<dim3(SEQ / 128, NH, BATCH * NSPLIT), 128, A_SMEM_B>>>(
        qq, kk, vv, opart, lpart);

    // out projection with fused split-K reduce in A staging -> fp32 output
    gemm16<2><<<dim3(DMODEL / 64, ROWS / 128), 256, G_SMEM_B>>>(
        opart, woutT, out, nullptr, nullptr, nullptr, nullptr, lpart,
        ROWS, DMODEL, DINNER);
}

// round 16
// speedup vs baseline: 1.0917x; 1.0917x over previous
#include <cuda_runtime.h>
#include <cuda_fp16.h>
#include <math.h>
#include <stdint.h>

constexpr int BATCH  = 4;
constexpr int SEQ    = 2048;
constexpr int DMODEL = 512;
constexpr int NH     = 8;
constexpr int HD     = 64;
constexpr int DINNER = NH * HD;        // 512
constexpr int ROWS   = BATCH * SEQ;    // 8192

constexpr int NSPLIT = 2;              // attention split-K factor
constexpr size_t OSZ = (size_t)ROWS * DINNER;
constexpr int LSZ = BATCH * NH * SEQ;

// Scratch (global device arrays; no allocations allowed)
__device__ __half g_xn16[ROWS * DMODEL];
__device__ __half g_wqkvT[3 * DINNER * DMODEL];   // [N=1536][K=512]
__device__ __half g_woutT[DMODEL * DINNER];       // [N=512][K=512]
__device__ float2 g_rope[SEQ * 32];               // (cos, sin) per (n, pair)
__device__ __half g_q16[(size_t)BATCH * NH * SEQ * HD];
__device__ __half g_k16[(size_t)BATCH * NH * SEQ * HD];
__device__ __half g_v16[(size_t)BATCH * NH * SEQ * HD];
__device__ __half g_opart[NSPLIT * OSZ];          // normalized fp16 partials
__device__ float  g_lpart[NSPLIT * LSZ];          // split-K partial l
__device__ __half g_attn16[ROWS * DINNER];

// ===========================================================================
// Helpers
// ===========================================================================
__device__ __forceinline__ float ex2(float x) {
    float y;
    asm("ex2.approx.f32 %0, %1;" : "=f"(y) : "f"(x));
    return y;
}

__device__ __forceinline__ uint32_t smem_u32(const void* p) {
    uint32_t a;
    asm("{ .reg .u64 t; cvta.to.shared.u64 t, %1; cvt.u32.u64 %0, t; }"
        : "=r"(a) : "l"(p));
    return a;
}

__device__ __forceinline__ uint32_t h2pack(float a, float b) {
    __half2 h = __floats2half2_rn(a, b);
    return *(uint32_t*)&h;
}

__device__ __forceinline__ void mma_f16(float d[4], const uint32_t a[4],
                                        uint32_t b0, uint32_t b1) {
    asm volatile(
        "mma.sync.aligned.m16n8k16.row.col.f32.f16.f16.f32 "
        "{%0,%1,%2,%3}, {%4,%5,%6,%7}, {%8,%9}, {%0,%1,%2,%3};"
        : "+f"(d[0]), "+f"(d[1]), "+f"(d[2]), "+f"(d[3])
        : "r"(a[0]), "r"(a[1]), "r"(a[2]), "r"(a[3]), "r"(b0), "r"(b1));
}

__device__ __forceinline__ void ldm_x4(uint32_t r[4], uint32_t addr) {
    asm volatile(
        "ldmatrix.sync.aligned.m8n8.x4.shared.b16 {%0,%1,%2,%3}, [%4];"
        : "=r"(r[0]), "=r"(r[1]), "=r"(r[2]), "=r"(r[3]) : "r"(addr));
}

__device__ __forceinline__ void ldm_x4t(uint32_t r[4], uint32_t addr) {
    asm volatile(
        "ldmatrix.sync.aligned.m8n8.x4.trans.shared.b16 {%0,%1,%2,%3}, [%4];"
        : "=r"(r[0]), "=r"(r[1]), "=r"(r[2]), "=r"(r[3]) : "r"(addr));
}

__device__ __forceinline__ void cp16(uint32_t dst, const void* src) {
    asm volatile("cp.async.cg.shared.global [%0], [%1], 16;"
                 :: "r"(dst), "l"(src));
}
#define CP_COMMIT() asm volatile("cp.async.commit_group;" ::: "memory")
#define CP_WAIT2()  asm volatile("cp.async.wait_group 2;" ::: "memory")
#define CP_WAIT1()  asm volatile("cp.async.wait_group 1;" ::: "memory")
#define CP_WAIT0()  asm volatile("cp.async.wait_group 0;" ::: "memory")

// ===========================================================================
// Fused prep kernel: block-dispatched rmsnorm (2 rows/block, float4) /
// wtrans x2 / rope table.
// ===========================================================================
__device__ __forceinline__ void wtrans_body(const float* __restrict__ W,
                                            __half* __restrict__ Wt,
                                            int K, int N, int n0, int k0,
                                            float (*ts)[65]) {
    int tid = threadIdx.x;
    #pragma unroll
    for (int e = 0; e < 16; e++) {
        int idx = tid + e * 256;
        int kl = idx >> 6, nl = idx & 63;
        ts[kl][nl] = W[(size_t)(k0 + kl) * N + n0 + nl];
    }
    __syncthreads();
    #pragma unroll
    for (int e = 0; e < 8; e++) {
        int idx = tid + e * 256;
        int nl = idx >> 5, kp = idx & 31;
        *(__half2*)(Wt + (size_t)(n0 + nl) * K + k0 + 2 * kp) =
            __floats2half2_rn(ts[2 * kp][nl], ts[2 * kp + 1][nl]);
    }
}

__global__ void prep_kernel(const float* __restrict__ x,
                            const float* __restrict__ gamma,
                            const float* __restrict__ w_qkv,
                            const float* __restrict__ w_out,
                            __half* __restrict__ xn,
                            __half* __restrict__ wqkvT,
                            __half* __restrict__ woutT,
                            float2* __restrict__ rope) {
    __shared__ float ts[64][65];
    int blk = blockIdx.x, t = threadIdx.x;

    if (blk < ROWS / 2) {
        // RMSNorm: 2 rows per block, float4 loads. Warps 0-3 row0, 4-7 row1.
        int row = blk * 2 + (t >> 7);
        int tr = t & 127;
        float4 v = ((const float4*)(x + (size_t)row * DMODEL))[tr];
        float4 gv = ((const float4*)gamma)[tr];
        float local = v.x * v.x + v.y * v.y + v.z * v.z + v.w * v.w;
        #pragma unroll
        for (int o = 16; o > 0; o >>= 1)
            local += __shfl_xor_sync(0xffffffffu, local, o);
        int wid = t >> 5;
        if ((t & 31) == 0) ts[0][wid] = local;
        __syncthreads();
        int base = (t >> 7) * 4;
        float s = ts[0][base] + ts[0][base + 1] + ts[0][base + 2]
                + ts[0][base + 3];
        float scale = 22.62741699796952f / fmaxf(sqrtf(s), 1e-8f);  // sqrt(512)
        uint2 o2;
        o2.x = h2pack(v.x * scale * gv.x, v.y * scale * gv.y);
        o2.y = h2pack(v.z * scale * gv.z, v.w * scale * gv.w);
        *(uint2*)(xn + (size_t)row * DMODEL + tr * 4) = o2;
    } else if (blk < ROWS / 2 + 192) {
        int i = blk - ROWS / 2;                 // 24 x 8 tiles
        wtrans_body(w_qkv, wqkvT, DMODEL, 3 * DINNER,
                    (i % 24) * 64, (i / 24) * 64, ts);
    } else if (blk < ROWS / 2 + 192 + 64) {
        int i = blk - ROWS / 2 - 192;           // 8 x 8 tiles
        wtrans_body(w_out, woutT, DMODEL, DINNER,
                    (i & 7) * 64, (i >> 3) * 64, ts);
    } else {
        int gid = (blk - (ROWS / 2 + 256)) * 256 + t;
        int p = gid & 31, n = gid >> 5;
        float invf = powf(10000.0f, -(float)p / 32.0f);
        float sn, cs;
        sincosf((float)n * invf, &sn, &cs);
        rope[gid] = make_float2(cs, sn);
    }
}

// ===========================================================================
// fp16 tensor GEMM (narrow): CTA 128(M) x 64(N), BK=64, 256 threads
// (8 warps 4x2), warp tile 32x32, 3 CTAs/SM, 2-stage cp.async. 144B rows.
// ROPE=true: fused RoPE (table) epilogue -> q/k/v fp16. Used for QKV (big grid).
// ===========================================================================
constexpr int G_A_B     = 128 * 144;               // 18432
constexpr int G_STAGE_B = G_A_B + 64 * 144;        // 27648
constexpr int G_SMEM_B  = 2 * G_STAGE_B;           // 55296

__global__ void __launch_bounds__(256, 3) gemm16_rope(
        const __half* __restrict__ A, const __half* __restrict__ Wt,
        __half* __restrict__ qo, __half* __restrict__ ko,
        __half* __restrict__ vo, const float2* __restrict__ rope,
        int M, int N, int K) {
    extern __shared__ char smraw[];
    uint32_t sb = smem_u32(smraw);
    int tid = threadIdx.x, lane = tid & 31, wid = tid >> 5;
    int g = lane >> 2, tig = lane & 3;
    int m0 = blockIdx.y * 128, n0 = blockIdx.x * 64;
    int wm = (wid & 3) * 32, wn = (wid >> 2) * 32;

    float acc[2][4][4] = {};
    int nst = K / 64;

    #pragma unroll
    for (int st = 0; st < 2; st++) {
        uint32_t base = sb + st * G_STAGE_B;
        int k0 = st * 64;
        #pragma unroll
        for (int e = 0; e < 4; e++) {
            int c = tid + e * 256;
            cp16(base + (c >> 3) * 144 + (c & 7) * 16,
                 A + (size_t)(m0 + (c >> 3)) * K + k0 + (c & 7) * 8);
        }
        #pragma unroll
        for (int e = 0; e < 2; e++) {
            int c = tid + e * 256;
            cp16(base + G_A_B + (c >> 3) * 144 + (c & 7) * 16,
                 Wt + (size_t)(n0 + (c >> 3)) * K + k0 + (c & 7) * 8);
        }
        CP_COMMIT();
    }

    for (int st = 0; st < nst; st++) {
        if (st + 2 <= nst) { CP_WAIT1(); } else { CP_WAIT0(); }
        __syncthreads();

        uint32_t sa_ = sb + (st & 1) * G_STAGE_B;
        uint32_t aoff = sa_ + (wm + (lane & 15)) * 144 + (lane >> 4) * 16;
        uint32_t boff = sa_ + G_A_B + (wn + (lane & 15)) * 144
                      + (lane >> 4) * 16;

        #pragma unroll
        for (int kc = 0; kc < 4; kc++) {
            uint32_t bf0[4], bf1[4];
            ldm_x4(bf0, boff + kc * 32);
            ldm_x4(bf1, boff + 16 * 144 + kc * 32);
            #pragma unroll
            for (int mt = 0; mt < 2; mt++) {
                uint32_t af[4];
                ldm_x4(af, aoff + mt * 16 * 144 + kc * 32);
                mma_f16(acc[mt][0], af, bf0[0], bf0[2]);
                mma_f16(acc[mt][1], af, bf0[1], bf0[3]);
                mma_f16(acc[mt][2], af, bf1[0], bf1[2]);
                mma_f16(acc[mt][3], af, bf1[1], bf1[3]);
            }
        }
        __syncthreads();

        if (st + 2 < nst) {
            uint32_t base = sb + (st & 1) * G_STAGE_B;
            int k0 = (st + 2) * 64;
            #pragma unroll
            for (int e = 0; e < 4; e++) {
                int c = tid + e * 256;
                cp16(base + (c >> 3) * 144 + (c & 7) * 16,
                     A + (size_t)(m0 + (c >> 3)) * K + k0 + (c & 7) * 8);
            }
            #pragma unroll
            for (int e = 0; e < 2; e++) {
                int c = tid + e * 256;
                cp16(base + G_A_B + (c >> 3) * 144 + (c & 7) * 16,
                     Wt + (size_t)(n0 + (c >> 3)) * K + k0 + (c & 7) * 8);
            }
            CP_COMMIT();
        }
    }

    int which = n0 >> 9;
    const float QS = 0.125f * 1.44269504088896341f;
    #pragma unroll
    for (int nb = 0; nb < 4; nb++) {
        int cg = n0 + wn + nb * 8 + 2 * tig;
        int h = (cg & 511) >> 6, d = cg & 63;
        int p = d >> 1;
        #pragma unroll
        for (int mt = 0; mt < 2; mt++) {
            int r0 = m0 + wm + mt * 16 + g;
            int n_ = r0 & (SEQ - 1), b_ = r0 >> 11;
            size_t o0 = ((size_t)(b_ * NH + h) * SEQ + n_) * HD + d;
            float* t = acc[mt][nb];
            if (which == 2) {
                *(__half2*)(vo + o0) = __floats2half2_rn(t[0], t[1]);
                *(__half2*)(vo + o0 + 8 * HD) = __floats2half2_rn(t[2], t[3]);
            } else {
                float2 cs0 = rope[n_ * 32 + p];
                float2 cs1 = rope[(n_ + 8) * 32 + p];
                if (which == 0) {
                    *(__half2*)(qo + o0) = __floats2half2_rn(
                        (t[0] * cs0.x - t[1] * cs0.y) * QS,
                        (t[1] * cs0.x + t[0] * cs0.y) * QS);
                    *(__half2*)(qo + o0 + 8 * HD) = __floats2half2_rn(
                        (t[2] * cs1.x - t[3] * cs1.y) * QS,
                        (t[3] * cs1.x + t[2] * cs1.y) * QS);
                } else {
                    *(__half2*)(ko + o0) = __floats2half2_rn(
                        t[0] * cs0.x - t[1] * cs0.y,
                        t[1] * cs0.x + t[0] * cs0.y);
                    *(__half2*)(ko + o0 + 8 * HD) = __floats2half2_rn(
                        t[2] * cs1.x - t[3] * cs1.y,
                        t[3] * cs1.x + t[2] * cs1.y);
                }
            }
        }
    }
}

// ===========================================================================
// fp16 tensor GEMM (wide): CTA 128x128, BK=64, 256 threads (8 warps 2x4),
// warp tile 64x32, 3-stage cp.async, 2 CTAs/SM. For the out-projection:
// grid 4x64 = 256 CTAs = 0.86 waves (single wave, no quantization).
// ===========================================================================
constexpr int W_STAGE_B = 2 * 128 * 144;           // 36864
constexpr int W_SMEM_B  = 3 * W_STAGE_B;           // 110592

__global__ void __launch_bounds__(256, 2) gemm16_wide(
        const __half* __restrict__ A, const __half* __restrict__ Wt,
        float* __restrict__ C, int M, int N, int K) {
    extern __shared__ char smraw[];
    uint32_t sb = smem_u32(smraw);
    int tid = threadIdx.x, lane = tid & 31, wid = tid >> 5;
    int g = lane >> 2, tig = lane & 3;
    int m0 = blockIdx.y * 128, n0 = blockIdx.x * 128;
    int wm = (wid & 1) * 64, wn = (wid >> 1) * 32;

    int crow[4], cch[4];
    #pragma unroll
    for (int e = 0; e < 4; e++) {
        int c = tid + e * 256;
        crow[e] = c >> 3;
        cch[e] = c & 7;
    }

    float acc[4][4][4] = {};
    int nst = K / 64;

    #pragma unroll
    for (int st = 0; st < 3; st++) {
        uint32_t base = sb + st * W_STAGE_B;
        int k0 = st * 64;
        #pragma unroll
        for (int e = 0; e < 4; e++) {
            cp16(base + crow[e] * 144 + cch[e] * 16,
                 A + (size_t)(m0 + crow[e]) * K + k0 + cch[e] * 8);
            cp16(base + 128 * 144 + crow[e] * 144 + cch[e] * 16,
                 Wt + (size_t)(n0 + crow[e]) * K + k0 + cch[e] * 8);
        }
        CP_COMMIT();
    }

    for (int st = 0; st < nst; st++) {
        if (st + 3 <= nst) { CP_WAIT2(); }
        else if (st + 2 <= nst) { CP_WAIT1(); }
        else { CP_WAIT0(); }
        __syncthreads();

        uint32_t sa_ = sb + (st % 3) * W_STAGE_B;
        uint32_t aoff = sa_ + (wm + (lane & 15)) * 144 + (lane >> 4) * 16;
        uint32_t boff = sa_ + 128 * 144 + (wn + (lane & 15)) * 144
                      + (lane >> 4) * 16;

        #pragma unroll
        for (int kc = 0; kc < 4; kc++) {
            uint32_t bf0[4], bf1[4];
            ldm_x4(bf0, boff + kc * 32);
            ldm_x4(bf1, boff + 16 * 144 + kc * 32);
            #pragma unroll
            for (int mt = 0; mt < 4; mt++) {
                uint32_t af[4];
                ldm_x4(af, aoff + mt * 16 * 144 + kc * 32);
                mma_f16(acc[mt][0], af, bf0[0], bf0[2]);
                mma_f16(acc[mt][1], af, bf0[1], bf0[3]);
                mma_f16(acc[mt][2], af, bf1[0], bf1[2]);
                mma_f16(acc[mt][3], af, bf1[1], bf1[3]);
            }
        }
        __syncthreads();

        if (st + 3 < nst) {
            uint32_t base = sb + (st % 3) * W_STAGE_B;
            int k0 = (st + 3) * 64;
            #pragma unroll
            for (int e = 0; e < 4; e++) {
                cp16(base + crow[e] * 144 + cch[e] * 16,
                     A + (size_t)(m0 + crow[e]) * K + k0 + cch[e] * 8);
                cp16(base + 128 * 144 + crow[e] * 144 + cch[e] * 16,
                     Wt + (size_t)(n0 + crow[e]) * K + k0 + cch[e] * 8);
            }
            CP_COMMIT();
        }
    }

    #pragma unroll
    for (int mt = 0; mt < 4; mt++)
        #pragma unroll
        for (int nb = 0; nb < 4; nb++) {
            int r = m0 + wm + mt * 16 + g;
            int c = n0 + wn + nb * 8 + 2 * tig;
            float* t = acc[mt][nb];
            *(float2*)&C[(size_t)r * N + c]       = make_float2(t[0], t[1]);
            *(float2*)&C[(size_t)(r + 8) * N + c] = make_float2(t[2], t[3]);
        }
}

// ===========================================================================
// fp16 tensor flash attention, split-K=2, one-pass no-max softmax.
// CTA: 128 queries x 1024 keys (16 tiles); 4 warps x 32 rows; 3-stage
// cp.async K/V. P never touches smem. Writes NORMALIZED fp16 O partial
// (O_s / l_s) + fp32 l. 3 CTAs/SM.
// ===========================================================================
constexpr int KT_SPLIT  = SEQ / 64 / NSPLIT;     // 16 key tiles per split
constexpr int A_STAGE_B = 2 * 64 * 144;          // K(9216)+V(9216) bytes
constexpr int A_SMEM_B  = 3 * A_STAGE_B;         // 55296 bytes

__global__ void __launch_bounds__(128, 3) attn16(
        const __half* __restrict__ q, const __half* __restrict__ k,
        const __half* __restrict__ v, __half* __restrict__ opart,
        float* __restrict__ lpart) {
    extern __shared__ char smraw[];
    uint32_t sb = smem_u32(smraw);

    int tid = threadIdx.x, lane = tid & 31, w = tid >> 5;
    int g = lane >> 2, tig = lane & 3;
    int wq = w * 32;

    int q0 = blockIdx.x * 128;
    int h = blockIdx.y;
    int b = blockIdx.z >> 1, sp = blockIdx.z & 1;
    int tbase = sp * KT_SPLIT;

    const __half* qb = q + ((size_t)(b * NH + h)) * SEQ * HD;
    const __half* kb = k + ((size_t)(b * NH + h)) * SEQ * HD;
    const __half* vb = v + ((size_t)(b * NH + h)) * SEQ * HD;

    int crow[4], cch[4];
    #pragma unroll
    for (int e = 0; e < 4; e++) {
        int c = tid + e * 128;
        crow[e] = c >> 3;
        cch[e] = c & 7;
    }

    // Q fragments in registers (pre-scaled fp16 by producer)
    uint32_t qa[2][4][4];
    #pragma unroll
    for (int mb = 0; mb < 2; mb++) {
        const uint32_t* q0r =
            (const uint32_t*)(qb + (size_t)(q0 + wq + mb * 16 + g) * HD);
        const uint32_t* q8r =
            (const uint32_t*)(qb + (size_t)(q0 + wq + mb * 16 + g + 8) * HD);
        #pragma unroll
        for (int kc = 0; kc < 4; kc++) {
            qa[mb][kc][0] = q0r[kc * 8 + tig];
            qa[mb][kc][1] = q8r[kc * 8 + tig];
            qa[mb][kc][2] = q0r[kc * 8 + 4 + tig];
            qa[mb][kc][3] = q8r[kc * 8 + 4 + tig];
        }
    }

    float oa[2][8][4] = {};
    float lr[2][2] = {};

    #pragma unroll
    for (int st = 0; st < 3; st++) {
        uint32_t base = sb + st * A_STAGE_B;
        #pragma unroll
        for (int e = 0; e < 4; e++) {
            uint32_t d = base + crow[e] * 144 + cch[e] * 16;
            cp16(d, kb + (size_t)((tbase + st) * 64 + crow[e]) * HD
                    + cch[e] * 8);
            cp16(d + 64 * 144,
                 vb + (size_t)((tbase + st) * 64 + crow[e]) * HD + cch[e] * 8);
        }
        CP_COMMIT();
    }

    for (int kt = 0; kt < KT_SPLIT; kt++) {
        if (kt + 3 <= KT_SPLIT) { CP_WAIT2(); }
        else if (kt + 2 <= KT_SPLIT) { CP_WAIT1(); }
        else { CP_WAIT0(); }
        __syncthreads();

        uint32_t kst = sb + (kt % 3) * A_STAGE_B;
        uint32_t kfrag = kst + (lane & 15) * 144 + (lane >> 4) * 16;
        uint32_t vfrag = kst + 64 * 144 + (lane & 15) * 144 + (lane >> 4) * 16;

        #pragma unroll
        for (int hc = 0; hc < 2; hc++) {     // two 32-key halves
            float sa[2][4][4] = {};
            #pragma unroll
            for (int nt16 = 0; nt16 < 2; nt16++) {
                #pragma unroll
                for (int kc = 0; kc < 4; kc++) {
                    uint32_t f[4];
                    ldm_x4(f, kfrag + (hc * 32 + nt16 * 16) * 144 + kc * 32);
                    #pragma unroll
                    for (int mb = 0; mb < 2; mb++) {
                        mma_f16(sa[mb][nt16 * 2],     qa[mb][kc], f[0], f[2]);
                        mma_f16(sa[mb][nt16 * 2 + 1], qa[mb][kc], f[1], f[3]);
                    }
                }
            }

            #pragma unroll
            for (int mb = 0; mb < 2; mb++)
                #pragma unroll
                for (int nb = 0; nb < 4; nb++) {
                    sa[mb][nb][0] = ex2(sa[mb][nb][0]);
                    sa[mb][nb][1] = ex2(sa[mb][nb][1]);
                    sa[mb][nb][2] = ex2(sa[mb][nb][2]);
                    sa[mb][nb][3] = ex2(sa[mb][nb][3]);
                    lr[mb][0] += sa[mb][nb][0] + sa[mb][nb][1];
                    lr[mb][1] += sa[mb][nb][2] + sa[mb][nb][3];
                }

            #pragma unroll
            for (int kcl = 0; kcl < 2; kcl++) {
                uint32_t paf[2][4];
                #pragma unroll
                for (int mb = 0; mb < 2; mb++) {
                    paf[mb][0] = h2pack(sa[mb][2 * kcl][0], sa[mb][2 * kcl][1]);
                    paf[mb][1] = h2pack(sa[mb][2 * kcl][2], sa[mb][2 * kcl][3]);
                    paf[mb][2] = h2pack(sa[mb][2 * kcl + 1][0],
                                        sa[mb][2 * kcl + 1][1]);
                    paf[mb][3] = h2pack(sa[mb][2 * kcl + 1][2],
                                        sa[mb][2 * kcl + 1][3]);
                }
                #pragma unroll
                for (int ntp = 0; ntp < 4; ntp++) {
                    uint32_t vf[4];
                    ldm_x4t(vf, vfrag + (hc * 32 + kcl * 16) * 144 + ntp * 32);
                    #pragma unroll
                    for (int mb = 0; mb < 2; mb++) {
                        mma_f16(oa[mb][ntp * 2],     paf[mb], vf[0], vf[1]);
                        mma_f16(oa[mb][ntp * 2 + 1], paf[mb], vf[2], vf[3]);
                    }
                }
            }
        }
        __syncthreads();

        if (kt + 3 < KT_SPLIT) {
            uint32_t base = sb + (kt % 3) * A_STAGE_B;
            #pragma unroll
            for (int e = 0; e < 4; e++) {
                uint32_t d = base + crow[e] * 144 + cch[e] * 16;
                cp16(d, kb + (size_t)((tbase + kt + 3) * 64 + crow[e]) * HD
                        + cch[e] * 8);
                cp16(d + 64 * 144,
                     vb + (size_t)((tbase + kt + 3) * 64 + crow[e]) * HD
                        + cch[e] * 8);
            }
            CP_COMMIT();
        }
    }

    // Write NORMALIZED fp16 partial O + fp32 partial l
    __half* od = opart + (size_t)sp * OSZ;
    float* ld = lpart + sp * LSZ;
    #pragma unroll
    for (int mb = 0; mb < 2; mb++) {
        float l0 = lr[mb][0], l1 = lr[mb][1];
        l0 += __shfl_xor_sync(0xffffffffu, l0, 1);
        l0 += __shfl_xor_sync(0xffffffffu, l0, 2);
        l1 += __shfl_xor_sync(0xffffffffu, l1, 1);
        l1 += __shfl_xor_sync(0xffffffffu, l1, 2);
        float inv0 = 1.0f / l0, inv1 = 1.0f / l1;
        int rq = q0 + wq + mb * 16 + g;
        size_t base0 = ((size_t)b * SEQ + rq) * DINNER + h * HD;
        #pragma unroll
        for (int nb = 0; nb < 8; nb++) {
            int c = nb * 8 + 2 * tig;
            *(uint32_t*)(od + base0 + c) =
                h2pack(oa[mb][nb][0] * inv0, oa[mb][nb][1] * inv0);
            *(uint32_t*)(od + base0 + (size_t)8 * DINNER + c) =
                h2pack(oa[mb][nb][2] * inv1, oa[mb][nb][3] * inv1);
        }
        if (tig == 0) {
            ld[(b * NH + h) * SEQ + rq]     = l0;
            ld[(b * NH + h) * SEQ + rq + 8] = l1;
        }
    }
}

// ===========================================================================
// Split-K reduce: attn16 = sum_s (l_s / sum l) * opart_s, fp16 out.
// ===========================================================================
__global__ void reduce_attn(const __half* __restrict__ op,
                            const float* __restrict__ lp,
                            __half* __restrict__ out) {
    int idx = blockIdx.x * 256 + threadIdx.x;    // over ROWS*DINNER/8
    size_t o = (size_t)idx * 8;
    int row = (int)(o >> 9);                     // / DINNER
    int c = (int)(o & (DINNER - 1));
    int h = c >> 6;
    int n = row & (SEQ - 1), b = row >> 11;
    int li = (b * NH + h) * SEQ + n;

    float ls[NSPLIT], lt = 0.f;
    #pragma unroll
    for (int s = 0; s < NSPLIT; s++) { ls[s] = lp[s * LSZ + li]; lt += ls[s]; }
    float invt = 1.0f / lt;

    float a[8] = {};
    #pragma unroll
    for (int s = 0; s < NSPLIT; s++) {
        float wgt = ls[s] * invt;
        uint4 hv = *(const uint4*)(op + s * OSZ + o);
        const __half2* h2 = (const __half2*)&hv;
        #pragma unroll
        for (int j = 0; j < 4; j++) {
            float2 f = __half22float2(h2[j]);
            a[2 * j]     += wgt * f.x;
            a[2 * j + 1] += wgt * f.y;
        }
    }
    uint4 r;
    r.x = h2pack(a[0], a[1]);
    r.y = h2pack(a[2], a[3]);
    r.z = h2pack(a[4], a[5]);
    r.w = h2pack(a[6], a[7]);
    *(uint4*)(out + o) = r;
}

// ===========================================================================
extern "C" void kernel_launch(void* const* d_in, const int* in_sizes, int n_in,
                              void* d_out, int out_size) {
    const float* x      = (const float*)d_in[0];
    const float* gamma  = (const float*)d_in[1];
    const float* w_qkv  = (const float*)d_in[2];
    const float* w_out  = (const float*)d_in[3];
    float* out = (float*)d_out;

    __half *xn, *wqkvT, *woutT, *qq, *kk, *vv, *opart, *attn;
    float *lpart;
    float2 *rope;
    cudaGetSymbolAddress((void**)&xn,    g_xn16);
    cudaGetSymbolAddress((void**)&wqkvT, g_wqkvT);
    cudaGetSymbolAddress((void**)&woutT, g_woutT);
    cudaGetSymbolAddress((void**)&rope,  g_rope);
    cudaGetSymbolAddress((void**)&qq,    g_q16);
    cudaGetSymbolAddress((void**)&kk,    g_k16);
    cudaGetSymbolAddress((void**)&vv,    g_v16);
    cudaGetSymbolAddress((void**)&opart, g_opart);
    cudaGetSymbolAddress((void**)&lpart, g_lpart);
    cudaGetSymbolAddress((void**)&attn,  g_attn16);

    cudaFuncSetAttribute(gemm16_rope,
                         cudaFuncAttributeMaxDynamicSharedMemorySize, G_SMEM_B);
    cudaFuncSetAttribute(gemm16_wide,
                         cudaFuncAttributeMaxDynamicSharedMemorySize, W_SMEM_B);
    cudaFuncSetAttribute(attn16,
                         cudaFuncAttributeMaxDynamicSharedMemorySize, A_SMEM_B);

    // Fused prep: rmsnorm (2 rows/block) + weight transposes + rope table
    prep_kernel<<<ROWS / 2 + 192 + 64 + 256, 256>>>(
        x, gamma, w_qkv, w_out, xn, wqkvT, woutT, rope);

    // QKV GEMM with fused RoPE/split/fp16 epilogue (128x64, 3 CTA/SM)
    gemm16_rope<<<dim3(3 * DINNER / 64, ROWS / 128), 256, G_SMEM_B>>>(
        xn, wqkvT, qq, kk, vv, rope, ROWS, 3 * DINNER, DMODEL);

    // split-K=2 attention (fp16 normalized partials) + weighted reduce
    attn16<<<dim3(SEQ / 128, NH, BATCH * NSPLIT), 128, A_SMEM_B>>>(
        qq, kk, vv, opart, lpart);
    reduce_attn<<<ROWS * DINNER / (256 * 8), 256>>>(opart, lpart, attn);

    // out projection: wide 128x128 tiles -> single wave (256 CTAs)
    gemm16_wide<<<dim3(DMODEL / 128, ROWS / 128), 256, W_SMEM_B>>>(
        attn, woutT, out, ROWS, DMODEL, DINNER);
}